// round 8
// baseline (speedup 1.0000x reference)
#include <cuda_runtime.h>
#include <math_constants.h>

#define NSEQ 16          // B*H
#define SEQL 1024        // L
#define DIM  64          // D
#define CHK  128         // chunk size
#define NCHK (SEQL/CHK)  // 8
#define D2   128         // 2*DIM

__device__ float g_S[NSEQ*NCHK*D2*DIM];
__device__ float g_z[NSEQ*NCHK*D2];

__device__ __forceinline__ float4 relu4(float4 a){
    a.x = fmaxf(a.x,0.f); a.y = fmaxf(a.y,0.f);
    a.z = fmaxf(a.z,0.f); a.w = fmaxf(a.w,0.f);
    return a;
}
typedef unsigned long long u64c;
__device__ __forceinline__ u64c ffma2(u64c a, u64c b, u64c c){
    u64c d;
    asm("fma.rn.f32x2 %0, %1, %2, %3;" : "=l"(d) : "l"(a), "l"(b), "l"(c));
    return d;
}
__device__ __forceinline__ u64c pack2(float x, float y){
    u64c d;
    asm("mov.b64 %0, {%1, %2};" : "=l"(d) : "f"(x), "f"(y));
    return d;
}
__device__ __forceinline__ float2 unpack2(u64c d){
    float2 r;
    asm("mov.b64 {%0, %1}, %2;" : "=f"(r.x), "=f"(r.y) : "l"(d));
    return r;
}

// ---------------------------------------------------------------------------
// Kernel 1: S[d'][m] = sum_j kext[j][d'] * V[j][m];  z[d'] = sum_j kext[j][d']
// grid=128, block=512. 4x4 register tiles, f32x2.
// ---------------------------------------------------------------------------
__global__ void __launch_bounds__(512,1)
k1_chunk_sums(const float* __restrict__ k, const float* __restrict__ v) {
    const int blk = blockIdx.x;
    const int n = blk >> 3, c = blk & 7;
    extern __shared__ float sm[];
    float* kext = sm;             // [128 j][132]
    float* V    = sm + 128*132;   // [128 j][68]
    const int tid = threadIdx.x;
    const size_t base = ((size_t)n*SEQL + (size_t)c*CHK)*DIM;
    const float4* k4 = (const float4*)(k + base);
    const float4* v4 = (const float4*)(v + base);

    #pragma unroll
    for (int it = 0; it < 4; it++) {
        int idx = tid + 512*it;         // [j][f]
        int j = idx >> 4, f = idx & 15;
        float ang = 1.5707963268f * (float)(c*CHK + j + 1) * (1.f/(float)SEQL);
        float s = __sinf(ang), cc = __cosf(ang);
        float4 kk = relu4(k4[idx]);
        float4 vv = relu4(v4[idx]);
        *(float4*)&kext[j*132 + 4*f]      = make_float4(kk.x*s,  kk.y*s,  kk.z*s,  kk.w*s);
        *(float4*)&kext[j*132 + 64 + 4*f] = make_float4(kk.x*cc, kk.y*cc, kk.z*cc, kk.w*cc);
        *(float4*)&V[j*68 + 4*f] = vv;
    }
    __syncthreads();

    if (tid < D2) {
        float zz = 0.f;
        #pragma unroll 8
        for (int j = 0; j < CHK; j++) zz += kext[j*132 + tid];
        g_z[blk*D2 + tid] = zz;
    }

    const int td = tid >> 4, tm = tid & 15;      // 32 x 16
    const int d0 = td*4, m0 = tm*4;
    const float4* V4 = (const float4*)V;
    u64c acc2[2][4];
    #pragma unroll
    for (int r = 0; r < 2; r++)
        #pragma unroll
        for (int q2 = 0; q2 < 4; q2++) acc2[r][q2] = pack2(0.f,0.f);

    #pragma unroll 4
    for (int j = 0; j < CHK; j++) {
        float4 ka = *(const float4*)&kext[j*132 + d0];
        float4 vv = V4[j*17 + tm];
        u64c kp0 = pack2(ka.x,ka.y), kp1 = pack2(ka.z,ka.w);
        float vf[4] = {vv.x,vv.y,vv.z,vv.w};
        #pragma unroll
        for (int q2 = 0; q2 < 4; q2++) {
            u64c vd = pack2(vf[q2], vf[q2]);
            acc2[0][q2] = ffma2(kp0, vd, acc2[0][q2]);
            acc2[1][q2] = ffma2(kp1, vd, acc2[1][q2]);
        }
    }
    float4* oS = (float4*)(g_S + (size_t)blk*D2*DIM);
    #pragma unroll
    for (int r = 0; r < 2; r++) {
        float2 a0 = unpack2(acc2[r][0]);
        float2 a1 = unpack2(acc2[r][1]);
        float2 a2 = unpack2(acc2[r][2]);
        float2 a3 = unpack2(acc2[r][3]);
        oS[(d0+2*r)*16   + tm] = make_float4(a0.x,a1.x,a2.x,a3.x);
        oS[(d0+2*r+1)*16 + tm] = make_float4(a0.y,a1.y,a2.y,a3.y);
    }
}

// ---------------------------------------------------------------------------
// Kernel 2: exclusive prefix scan over chunks.
// ---------------------------------------------------------------------------
__global__ void k2_scan() {
    const int blk = blockIdx.x;
    const int n = blk >> 3, p = blk & 7;
    const int tid = threadIdx.x;
    float4* S4 = (float4*)g_S;
    const int col = p*256 + tid;
    float4 run = make_float4(0.f,0.f,0.f,0.f);
    #pragma unroll
    for (int c = 0; c < NCHK; c++) {
        size_t idx = (size_t)(n*NCHK + c)*2048 + col;
        float4 t = S4[idx];
        S4[idx] = run;
        run.x += t.x; run.y += t.y; run.z += t.z; run.w += t.w;
    }
    if (p == 0 && tid < D2) {
        float run2 = 0.f;
        #pragma unroll
        for (int c = 0; c < NCHK; c++) {
            int idx = (n*NCHK + c)*D2 + tid;
            float t = g_z[idx]; g_z[idx] = run2; run2 += t;
        }
    }
}

// ---------------------------------------------------------------------------
// Kernel 3: per-chunk output. grid=128, block=512.
// ---------------------------------------------------------------------------
__global__ void __launch_bounds__(512,1)
k3_out(const float* __restrict__ q, const float* __restrict__ k,
       const float* __restrict__ v, float* __restrict__ out) {
    const int blk = blockIdx.x;
    const int n = blk >> 3, c = blk & 7;
    extern __shared__ float sm[];
    float* qextT = sm;                       // [128 d'][132]
    float* kbuf  = qextT + 128*132;          // kextT; At overlay later
    float* V     = kbuf + 128*132 + 32;      // [128 j][68]
    float* U     = V + 128*68;               // [128 d'][68]
    float* zext  = U + 128*68;               // 128
    float* den   = zext + 128;               // 128
    const int tid = threadIdx.x;
    const size_t base = ((size_t)n*SEQL + (size_t)c*CHK)*DIM;
    const float4* q4 = (const float4*)(q + base);
    const float4* k4 = (const float4*)(k + base);
    const float4* v4 = (const float4*)(v + base);

    #pragma unroll
    for (int it = 0; it < 4; it++) {
        int idx = tid + 512*it;
        int j = idx & 127, f = idx >> 7;
        float ang = 1.5707963268f * (float)(c*CHK + j + 1) * (1.f/(float)SEQL);
        float s = __sinf(ang), cc = __cosf(ang);
        float4 qq = relu4(q4[j*16 + f]);
        float4 kk = relu4(k4[j*16 + f]);
        float4 vv = relu4(v4[j*16 + f]);
        int d = 4*f;
        qextT[(d+0)*132 + j] = qq.x*s;  qextT[(d+64)*132 + j] = qq.x*cc;
        qextT[(d+1)*132 + j] = qq.y*s;  qextT[(d+65)*132 + j] = qq.y*cc;
        qextT[(d+2)*132 + j] = qq.z*s;  qextT[(d+66)*132 + j] = qq.z*cc;
        qextT[(d+3)*132 + j] = qq.w*s;  qextT[(d+67)*132 + j] = qq.w*cc;
        kbuf[(d+0)*132 + j] = kk.x*s;   kbuf[(d+64)*132 + j] = kk.x*cc;
        kbuf[(d+1)*132 + j] = kk.y*s;   kbuf[(d+65)*132 + j] = kk.y*cc;
        kbuf[(d+2)*132 + j] = kk.z*s;   kbuf[(d+66)*132 + j] = kk.z*cc;
        kbuf[(d+3)*132 + j] = kk.w*s;   kbuf[(d+67)*132 + j] = kk.w*cc;
        *(float4*)&V[j*68 + d] = vv;
    }
    {
        const float4* gS4 = (const float4*)(g_S + (size_t)blk*D2*DIM);
        float4* U4w = (float4*)U;
        #pragma unroll
        for (int it = 0; it < 4; it++) {
            int i4 = tid + 512*it;
            int dp = i4 >> 4, mf = i4 & 15;
            U4w[dp*17 + mf] = gS4[i4];
        }
        if (tid < D2) zext[tid] = g_z[blk*D2 + tid];
    }
    __syncthreads();

    const float4* qT4 = (const float4*)qextT;
    const float4* kT4 = (const float4*)kbuf;

    // ---- Phase A: A[l][j], tiles 8(l) x 4(j). 16 x 32 thread grid. ----
    const int tl = tid >> 5, tj = tid & 31;
    const int l0 = tl*8, j0 = tj*4;
    u64c a2[4][4];                          // [jj][l-pair]
    #pragma unroll
    for (int jj = 0; jj < 4; jj++)
        #pragma unroll
        for (int lp = 0; lp < 4; lp++) a2[jj][lp] = pack2(0.f,0.f);

    #pragma unroll 4
    for (int dp = 0; dp < D2; dp++) {
        float4 qa = qT4[dp*33 + 2*tl];
        float4 qb = qT4[dp*33 + 2*tl + 1];
        float4 kA = kT4[dp*33 + tj];
        u64c qp[4] = { pack2(qa.x,qa.y), pack2(qa.z,qa.w),
                       pack2(qb.x,qb.y), pack2(qb.z,qb.w) };
        float kv[4] = {kA.x,kA.y,kA.z,kA.w};
        #pragma unroll
        for (int jj = 0; jj < 4; jj++) {
            u64c kd = pack2(kv[jj], kv[jj]);
            #pragma unroll
            for (int lp = 0; lp < 4; lp++)
                a2[jj][lp] = ffma2(kd, qp[lp], a2[jj][lp]);
        }
    }
    __syncthreads();

    // Masked transposed store At[j][l], XOR-swizzled float4 groups.
    float4* At4 = (float4*)kbuf;
    #pragma unroll
    for (int jj = 0; jj < 4; jj++) {
        int j = j0 + jj;
        int swz = (j >> 3) & 7;
        float w[8];
        #pragma unroll
        for (int lp = 0; lp < 4; lp++) {
            float2 p = unpack2(a2[jj][lp]);
            w[2*lp]   = (j <= l0 + 2*lp)     ? p.x : 0.f;
            w[2*lp+1] = (j <= l0 + 2*lp + 1) ? p.y : 0.f;
        }
        At4[j*33 + ((2*tl)   ^ swz)] = make_float4(w[0],w[1],w[2],w[3]);
        At4[j*33 + ((2*tl+1) ^ swz)] = make_float4(w[4],w[5],w[6],w[7]);
    }
    __syncthreads();

    // ---- Denominator ----
    if (tid < CHK) {
        const int l = tid;
        float dd = 0.f;
        #pragma unroll 8
        for (int j = 0; j < CHK; j++) {
            int swz = (j >> 3) & 7;
            dd += kbuf[j*132 + 4*((l>>2) ^ swz) + (l & 3)];
        }
        #pragma unroll 8
        for (int dp = 0; dp < D2; dp++)
            dd = fmaf(qextT[dp*132 + l], zext[dp], dd);
        den[l] = fmaxf(dd, 1e-6f);
    }
    __syncthreads();

    // ---- Phase B: out = A*V + qext*U. tiles 4(l) x 4(m). 32 x 16 grid. ----
    const int tlB = tid >> 4, tmB = tid & 15;
    const int lB0 = tlB*4, mB0 = tmB*4;
    u64c o2[2][4];                          // [l-pair][m]
    #pragma unroll
    for (int lp = 0; lp < 2; lp++)
        #pragma unroll
        for (int mm = 0; mm < 4; mm++) o2[lp][mm] = pack2(0.f,0.f);

    const float4* V4c = (const float4*)V;
    const float4* U4c = (const float4*)U;

    #pragma unroll 4
    for (int j = 0; j < CHK; j++) {
        int swz = (j >> 3) & 7;
        float4 A0 = At4[j*33 + (tlB ^ swz)];
        float4 vv = V4c[j*17 + tmB];
        u64c ap0 = pack2(A0.x,A0.y), ap1 = pack2(A0.z,A0.w);
        float vf[4] = {vv.x,vv.y,vv.z,vv.w};
        #pragma unroll
        for (int mm = 0; mm < 4; mm++) {
            u64c vd = pack2(vf[mm], vf[mm]);
            o2[0][mm] = ffma2(ap0, vd, o2[0][mm]);
            o2[1][mm] = ffma2(ap1, vd, o2[1][mm]);
        }
    }
    #pragma unroll 4
    for (int dp = 0; dp < D2; dp++) {
        float4 qa = qT4[dp*33 + tlB];
        float4 uu = U4c[dp*17 + tmB];
        u64c qp0 = pack2(qa.x,qa.y), qp1 = pack2(qa.z,qa.w);
        float uf[4] = {uu.x,uu.y,uu.z,uu.w};
        #pragma unroll
        for (int mm = 0; mm < 4; mm++) {
            u64c ud = pack2(uf[mm], uf[mm]);
            o2[0][mm] = ffma2(qp0, ud, o2[0][mm]);
            o2[1][mm] = ffma2(qp1, ud, o2[1][mm]);
        }
    }

    float* ob = out + base;
    #pragma unroll
    for (int lp = 0; lp < 2; lp++) {
        float2 p0 = unpack2(o2[lp][0]);
        float2 p1 = unpack2(o2[lp][1]);
        float2 p2 = unpack2(o2[lp][2]);
        float2 p3 = unpack2(o2[lp][3]);
        float r0 = 1.f / den[lB0 + 2*lp];
        float r1 = 1.f / den[lB0 + 2*lp + 1];
        *(float4*)&ob[(lB0+2*lp)*64   + mB0] = make_float4(p0.x*r0, p1.x*r0, p2.x*r0, p3.x*r0);
        *(float4*)&ob[(lB0+2*lp+1)*64 + mB0] = make_float4(p0.y*r1, p1.y*r1, p2.y*r1, p3.y*r1);
    }
}

extern "C" void kernel_launch(void* const* d_in, const int* in_sizes, int n_in,
                              void* d_out, int out_size) {
    const float* q = (const float*)d_in[0];
    const float* k = (const float*)d_in[1];
    const float* v = (const float*)d_in[2];
    float* out = (float*)d_out;

    const int smem1 = (128*132 + 128*68) * 4;                              // 102,400 B
    const int smem3 = (128*132 + 128*132 + 32 + 2*128*68 + 256) * 4;       // 205,952 B

    cudaFuncSetAttribute(k1_chunk_sums, cudaFuncAttributeMaxDynamicSharedMemorySize, smem1);
    cudaFuncSetAttribute(k3_out,        cudaFuncAttributeMaxDynamicSharedMemorySize, smem3);

    k1_chunk_sums<<<NSEQ*NCHK, 512, smem1>>>(k, v);
    k2_scan<<<NSEQ*NCHK, 256>>>();
    k3_out<<<NSEQ*NCHK, 512, smem3>>>(q, k, v, out);
}

// round 9
// speedup vs baseline: 1.0513x; 1.0513x over previous
#include <cuda_runtime.h>
#include <math_constants.h>

#define NSEQ 16          // B*H
#define SEQL 1024        // L
#define DIM  64          // D
#define CHK  128         // chunk size
#define NCHK (SEQL/CHK)  // 8
#define D2   128         // 2*DIM
#define NBLK (NSEQ*NCHK) // 128 blocks

__device__ float g_S[NSEQ*NCHK*D2*DIM];
__device__ float g_z[NSEQ*NCHK*D2];
__device__ unsigned int g_bar;   // zero-initialized; monotone across replays

__device__ __forceinline__ float4 relu4(float4 a){
    a.x = fmaxf(a.x,0.f); a.y = fmaxf(a.y,0.f);
    a.z = fmaxf(a.z,0.f); a.w = fmaxf(a.w,0.f);
    return a;
}
typedef unsigned long long u64c;
__device__ __forceinline__ u64c ffma2(u64c a, u64c b, u64c c){
    u64c d;
    asm("fma.rn.f32x2 %0, %1, %2, %3;" : "=l"(d) : "l"(a), "l"(b), "l"(c));
    return d;
}
__device__ __forceinline__ u64c pack2(float x, float y){
    u64c d;
    asm("mov.b64 %0, {%1, %2};" : "=l"(d) : "f"(x), "f"(y));
    return d;
}
__device__ __forceinline__ float2 unpack2(u64c d){
    float2 r;
    asm("mov.b64 {%0, %1}, %2;" : "=f"(r.x), "=f"(r.y) : "l"(d));
    return r;
}

__device__ __forceinline__ void grid_barrier() {
    __threadfence();
    __syncthreads();
    if (threadIdx.x == 0) {
        unsigned gen = atomicAdd(&g_bar, 1u);
        unsigned target = (gen / NBLK + 1u) * NBLK;
        while (atomicAdd(&g_bar, 0u) < target) { }
    }
    __syncthreads();
    __threadfence();
}

// ---------------------------------------------------------------------------
// Fused kernel. grid = 128 (one block per (seq, chunk)), block = 512.
// ---------------------------------------------------------------------------
__global__ void __launch_bounds__(512,1)
fused_cos_attn(const float* __restrict__ q, const float* __restrict__ k,
               const float* __restrict__ v, float* __restrict__ out) {
    const int blk = blockIdx.x;
    const int n = blk >> 3, c = blk & 7;
    extern __shared__ float sm[];
    float* qextT = sm;                       // [128 d'][132]
    float* kbuf  = qextT + 128*132;          // kextT [d'][132]; At overlay later
    float* V     = kbuf + 128*132 + 32;      // [128 j][68]
    float* U     = V + 128*68;               // [128 d'][68]
    float* zext  = U + 128*68;               // 128
    float* den   = zext + 128;               // 128
    const int tid = threadIdx.x;
    const size_t base = ((size_t)n*SEQL + (size_t)c*CHK)*DIM;
    const float4* q4 = (const float4*)(q + base);
    const float4* k4 = (const float4*)(k + base);
    const float4* v4 = (const float4*)(v + base);

    // ---- Stage q,k,v once: qextT/kextT transposed, V row-major ----
    {
        const int j = tid & 127;
        const float ang = 1.5707963268f * (float)(c*CHK + j + 1) * (1.f/(float)SEQL);
        const float s = __sinf(ang), cc = __cosf(ang);
        #pragma unroll
        for (int it = 0; it < 4; it++) {
            int f = (tid >> 7) + 4*it;       // 0..15
            float4 qq = relu4(q4[j*16 + f]);
            float4 kk = relu4(k4[j*16 + f]);
            float4 vv = relu4(v4[j*16 + f]);
            int d = 4*f;
            qextT[(d+0)*132 + j] = qq.x*s;  qextT[(d+64)*132 + j] = qq.x*cc;
            qextT[(d+1)*132 + j] = qq.y*s;  qextT[(d+65)*132 + j] = qq.y*cc;
            qextT[(d+2)*132 + j] = qq.z*s;  qextT[(d+66)*132 + j] = qq.z*cc;
            qextT[(d+3)*132 + j] = qq.w*s;  qextT[(d+67)*132 + j] = qq.w*cc;
            kbuf[(d+0)*132 + j] = kk.x*s;   kbuf[(d+64)*132 + j] = kk.x*cc;
            kbuf[(d+1)*132 + j] = kk.y*s;   kbuf[(d+65)*132 + j] = kk.y*cc;
            kbuf[(d+2)*132 + j] = kk.z*s;   kbuf[(d+66)*132 + j] = kk.z*cc;
            kbuf[(d+3)*132 + j] = kk.w*s;   kbuf[(d+67)*132 + j] = kk.w*cc;
            *(float4*)&V[j*68 + d] = vv;
        }
    }
    __syncthreads();

    // ---- z row sums: z[d'] = sum_j kextT[d'][j] ----
    if (tid < D2) {
        float zz = 0.f;
        #pragma unroll 8
        for (int j = 0; j < CHK; j++) zz += kbuf[tid*132 + j];
        g_z[blk*D2 + tid] = zz;
    }

    // ---- Chunk-state GEMM: S[d'][m] = sum_j kextT[d'][j] * V[j][m] ----
    {
        const int td = tid >> 4, tm = tid & 15;     // 32 x 16
        const int d0 = td*4;
        const float4* V4 = (const float4*)V;
        u64c acc2[2][4];
        #pragma unroll
        for (int r = 0; r < 2; r++)
            #pragma unroll
            for (int m = 0; m < 4; m++) acc2[r][m] = pack2(0.f,0.f);

        #pragma unroll 2
        for (int jb = 0; jb < CHK; jb += 4) {
            float kra[4][4];
            #pragma unroll
            for (int r = 0; r < 4; r++)
                *(float4*)kra[r] = *(const float4*)&kbuf[(d0+r)*132 + jb];
            float4 vv[4];
            #pragma unroll
            for (int i = 0; i < 4; i++) vv[i] = V4[(jb+i)*17 + tm];
            #pragma unroll
            for (int i = 0; i < 4; i++) {
                u64c kp0 = pack2(kra[0][i], kra[1][i]);
                u64c kp1 = pack2(kra[2][i], kra[3][i]);
                float vf[4] = {vv[i].x, vv[i].y, vv[i].z, vv[i].w};
                #pragma unroll
                for (int m = 0; m < 4; m++) {
                    u64c vd = pack2(vf[m], vf[m]);
                    acc2[0][m] = ffma2(kp0, vd, acc2[0][m]);
                    acc2[1][m] = ffma2(kp1, vd, acc2[1][m]);
                }
            }
        }
        float4* oS = (float4*)(g_S + (size_t)blk*D2*DIM);
        #pragma unroll
        for (int r = 0; r < 2; r++) {
            float2 a0 = unpack2(acc2[r][0]);
            float2 a1 = unpack2(acc2[r][1]);
            float2 a2 = unpack2(acc2[r][2]);
            float2 a3 = unpack2(acc2[r][3]);
            oS[(d0+2*r)*16   + tm] = make_float4(a0.x,a1.x,a2.x,a3.x);
            oS[(d0+2*r+1)*16 + tm] = make_float4(a0.y,a1.y,a2.y,a3.y);
        }
    }

    grid_barrier();

    // ---- Prefix state: U = sum of chunks 0..c-1 of this sequence ----
    {
        float4 ua[4];
        #pragma unroll
        for (int it = 0; it < 4; it++) ua[it] = make_float4(0.f,0.f,0.f,0.f);
        const float4* gSn = (const float4*)(g_S + (size_t)(n*NCHK)*D2*DIM);
        for (int cc = 0; cc < c; cc++) {
            const float4* p = gSn + (size_t)cc*2048;
            #pragma unroll
            for (int it = 0; it < 4; it++) {
                float4 t = p[tid + 512*it];
                ua[it].x += t.x; ua[it].y += t.y; ua[it].z += t.z; ua[it].w += t.w;
            }
        }
        float4* U4w = (float4*)U;
        #pragma unroll
        for (int it = 0; it < 4; it++) {
            int i4 = tid + 512*it;
            U4w[(i4 >> 4)*17 + (i4 & 15)] = ua[it];
        }
        if (tid < D2) {
            float zz = 0.f;
            for (int cc = 0; cc < c; cc++) zz += g_z[(n*NCHK + cc)*D2 + tid];
            zext[tid] = zz;
        }
    }

    const float4* qT4 = (const float4*)qextT;
    const float4* kT4 = (const float4*)kbuf;

    // ---- Phase A: A[l][j] = sum_d' qext[d'][l]*kext[d'][j], triangular warps ----
    // warp tile: 32 l x 32 j; warp (wl,wj) skipped when wj > wl.
    const int wid  = tid >> 5, lane = tid & 31;
    const int wl = wid >> 2, wj = wid & 3;
    const int tl = wl*4 + (lane >> 3);       // 0..15 (8 l per tile)
    const int tj = wj*8 + (lane & 7);        // 0..31 (4 j per tile)
    const int l0 = tl*8, j0 = tj*4;
    u64c a2[4][4];                            // [jj][l-pair]
    #pragma unroll
    for (int jj = 0; jj < 4; jj++)
        #pragma unroll
        for (int lp = 0; lp < 4; lp++) a2[jj][lp] = pack2(0.f,0.f);

    if (wj <= wl) {
        #pragma unroll 4
        for (int dp = 0; dp < D2; dp++) {
            float4 qa = qT4[dp*33 + 2*tl];
            float4 qb = qT4[dp*33 + 2*tl + 1];
            float4 kA = kT4[dp*33 + tj];
            u64c qp[4] = { pack2(qa.x,qa.y), pack2(qa.z,qa.w),
                           pack2(qb.x,qb.y), pack2(qb.z,qb.w) };
            float kv[4] = {kA.x,kA.y,kA.z,kA.w};
            #pragma unroll
            for (int jj = 0; jj < 4; jj++) {
                u64c kd = pack2(kv[jj], kv[jj]);
                #pragma unroll
                for (int lp = 0; lp < 4; lp++)
                    a2[jj][lp] = ffma2(kd, qp[lp], a2[jj][lp]);
            }
        }
    }
    __syncthreads();

    // Masked transposed store At[j][l], XOR-swizzled float4 groups.
    float4* At4 = (float4*)kbuf;
    #pragma unroll
    for (int jj = 0; jj < 4; jj++) {
        int j = j0 + jj;
        int swz = (j >> 3) & 7;
        float w[8];
        #pragma unroll
        for (int lp = 0; lp < 4; lp++) {
            float2 p = unpack2(a2[jj][lp]);
            w[2*lp]   = (j <= l0 + 2*lp)     ? p.x : 0.f;
            w[2*lp+1] = (j <= l0 + 2*lp + 1) ? p.y : 0.f;
        }
        At4[j*33 + ((2*tl)   ^ swz)] = make_float4(w[0],w[1],w[2],w[3]);
        At4[j*33 + ((2*tl+1) ^ swz)] = make_float4(w[4],w[5],w[6],w[7]);
    }
    __syncthreads();

    // ---- Denominator ----
    if (tid < CHK) {
        const int l = tid;
        float dd = 0.f;
        #pragma unroll 4
        for (int j = 0; j <= l; j++) {
            int swz = (j >> 3) & 7;
            dd += kbuf[j*132 + 4*((l>>2) ^ swz) + (l & 3)];
        }
        #pragma unroll 8
        for (int dp = 0; dp < D2; dp++)
            dd = fmaf(qextT[dp*132 + l], zext[dp], dd);
        den[l] = fmaxf(dd, 1e-6f);
    }
    __syncthreads();

    // ---- Phase B: out = A*V + qext*U, causal-truncated AV loop ----
    const int tlB = tid >> 4, tmB = tid & 15;
    const int lB0 = tlB*4, mB0 = tmB*4;
    u64c o2[2][4];
    #pragma unroll
    for (int lp = 0; lp < 2; lp++)
        #pragma unroll
        for (int mm = 0; mm < 4; mm++) o2[lp][mm] = pack2(0.f,0.f);

    const float4* V4c = (const float4*)V;
    const float4* U4c = (const float4*)U;

    const int jmax = lB0 + 4;                 // A[l][j]=0 for j>l
    #pragma unroll 4
    for (int j = 0; j < jmax; j++) {
        int swz = (j >> 3) & 7;
        float4 A0 = At4[j*33 + (tlB ^ swz)];
        float4 vv = V4c[j*17 + tmB];
        u64c ap0 = pack2(A0.x,A0.y), ap1 = pack2(A0.z,A0.w);
        float vf[4] = {vv.x,vv.y,vv.z,vv.w};
        #pragma unroll
        for (int mm = 0; mm < 4; mm++) {
            u64c vd = pack2(vf[mm], vf[mm]);
            o2[0][mm] = ffma2(ap0, vd, o2[0][mm]);
            o2[1][mm] = ffma2(ap1, vd, o2[1][mm]);
        }
    }
    #pragma unroll 4
    for (int dp = 0; dp < D2; dp++) {
        float4 qa = qT4[dp*33 + tlB];
        float4 uu = U4c[dp*17 + tmB];
        u64c qp0 = pack2(qa.x,qa.y), qp1 = pack2(qa.z,qa.w);
        float uf[4] = {uu.x,uu.y,uu.z,uu.w};
        #pragma unroll
        for (int mm = 0; mm < 4; mm++) {
            u64c ud = pack2(uf[mm], uf[mm]);
            o2[0][mm] = ffma2(qp0, ud, o2[0][mm]);
            o2[1][mm] = ffma2(qp1, ud, o2[1][mm]);
        }
    }

    float* ob = out + base;
    #pragma unroll
    for (int lp = 0; lp < 2; lp++) {
        float2 p0 = unpack2(o2[lp][0]);
        float2 p1 = unpack2(o2[lp][1]);
        float2 p2 = unpack2(o2[lp][2]);
        float2 p3 = unpack2(o2[lp][3]);
        float r0 = 1.f / den[lB0 + 2*lp];
        float r1 = 1.f / den[lB0 + 2*lp + 1];
        *(float4*)&ob[(lB0+2*lp)*64   + mB0] = make_float4(p0.x*r0, p1.x*r0, p2.x*r0, p3.x*r0);
        *(float4*)&ob[(lB0+2*lp+1)*64 + mB0] = make_float4(p0.y*r1, p1.y*r1, p2.y*r1, p3.y*r1);
    }
}

extern "C" void kernel_launch(void* const* d_in, const int* in_sizes, int n_in,
                              void* d_out, int out_size) {
    const float* q = (const float*)d_in[0];
    const float* k = (const float*)d_in[1];
    const float* v = (const float*)d_in[2];
    float* out = (float*)d_out;

    const int smem = (128*132 + 128*132 + 32 + 2*128*68 + 256) * 4;   // 205,952 B
    cudaFuncSetAttribute(fused_cos_attn, cudaFuncAttributeMaxDynamicSharedMemorySize, smem);
    fused_cos_attn<<<NBLK, 512, smem>>>(q, k, v, out);
}